// round 3
// baseline (speedup 1.0000x reference)
#include <cuda_runtime.h>
#include <math.h>

#define BB 4
#define SS 2048
#define DD 1024
#define HH 16
#define DH 64
#define KDIM 1024

// Scratch (allocation-free rule: __device__ globals)
__device__ float g_q[BB * HH * SS * DH];    // [B,H,S,dh] head-major, RoPE'd
__device__ float g_k[BB * HH * SS * DH];
__device__ float g_v[BB * HH * SS * DH];
__device__ float g_ctx[BB * SS * DD];       // [B,S,D] attention context

// ---------------------------------------------------------------------------
// SGEMM: Y = A[M,K] @ W[N,K]^T  (both K-contiguous).  M=8192, N=K=1024.
// 128x128 block tile, 8x8 per-thread microtile, 256 threads.
// epi: 0 = plain row-major store (final proj / direct to d_out)
//      1 = head-major store [B,H,S,dh]            (V)
//      2 = head-major store + fused RoPE          (Q, K)
// ---------------------------------------------------------------------------
__global__ void __launch_bounds__(256) gemm_kernel(
    const float* __restrict__ A, const float* __restrict__ W,
    float* __restrict__ Y, const int* __restrict__ pos, int epi)
{
    __shared__ float As[8][132];   // +4 pad: conflict-free transposed stores
    __shared__ float Bs[8][132];

    const int tid = threadIdx.x;
    const int bm  = blockIdx.y * 128;
    const int bn  = blockIdx.x * 128;
    const int lr  = tid >> 1;            // load row within tile (0..127)
    const int lk  = (tid & 1) * 4;       // k offset 0 or 4
    const int tx  = tid & 15;
    const int ty  = tid >> 4;

    const float* Ap = A + (long)(bm + lr) * KDIM + lk;
    const float* Wp = W + (long)(bn + lr) * KDIM + lk;

    float acc[8][8];
#pragma unroll
    for (int i = 0; i < 8; i++)
#pragma unroll
        for (int j = 0; j < 8; j++) acc[i][j] = 0.f;

    for (int k0 = 0; k0 < KDIM; k0 += 8) {
        float4 av = *(const float4*)(Ap + k0);
        float4 bv = *(const float4*)(Wp + k0);
        As[lk + 0][lr] = av.x; As[lk + 1][lr] = av.y;
        As[lk + 2][lr] = av.z; As[lk + 3][lr] = av.w;
        Bs[lk + 0][lr] = bv.x; Bs[lk + 1][lr] = bv.y;
        Bs[lk + 2][lr] = bv.z; Bs[lk + 3][lr] = bv.w;
        __syncthreads();
#pragma unroll
        for (int kk = 0; kk < 8; kk++) {
            float4 a0 = *(const float4*)&As[kk][ty * 8];
            float4 a1 = *(const float4*)&As[kk][ty * 8 + 4];
            float4 b0 = *(const float4*)&Bs[kk][tx * 8];
            float4 b1 = *(const float4*)&Bs[kk][tx * 8 + 4];
            float a[8] = {a0.x, a0.y, a0.z, a0.w, a1.x, a1.y, a1.z, a1.w};
            float b[8] = {b0.x, b0.y, b0.z, b0.w, b1.x, b1.y, b1.z, b1.w};
#pragma unroll
            for (int i = 0; i < 8; i++)
#pragma unroll
                for (int j = 0; j < 8; j++)
                    acc[i][j] = fmaf(a[i], b[j], acc[i][j]);
        }
        __syncthreads();
    }

    if (epi == 0) {
#pragma unroll
        for (int i = 0; i < 8; i++) {
            int m = bm + ty * 8 + i;
            float* yp = Y + (long)m * DD + bn + tx * 8;
            *(float4*)yp       = make_float4(acc[i][0], acc[i][1], acc[i][2], acc[i][3]);
            *(float4*)(yp + 4) = make_float4(acc[i][4], acc[i][5], acc[i][6], acc[i][7]);
        }
    } else {
#pragma unroll
        for (int i = 0; i < 8; i++) {
            int m  = bm + ty * 8 + i;
            int bq = m >> 11;          // m / 2048
            int sq = m & 2047;
            float p = 0.f;
            if (epi == 2) p = (float)pos[sq];
#pragma unroll
            for (int j = 0; j < 8; j += 2) {
                int n = bn + tx * 8 + j;   // even
                int h = n >> 6;
                int d = n & 63;            // even
                float x1 = acc[i][j], x2 = acc[i][j + 1];
                if (epi == 2) {
                    // inv_freq = 10000^(-(d/2)/32)
                    float fr  = powf(10000.f, -(float)(d >> 1) * (1.f / 32.f));
                    float ang = p * fr;
                    float c = cosf(ang), s = sinf(ang);
                    float o1 = x1 * c - x2 * s;
                    float o2 = x1 * s + x2 * c;
                    x1 = o1; x2 = o2;
                }
                long idx = ((long)(bq * HH + h) * SS + sq) * DH + d;
                Y[idx]     = x1;
                Y[idx + 1] = x2;
            }
        }
    }
}

// ---------------------------------------------------------------------------
// Causal flash attention.  One thread per query row; 128 rows/CTA.
// K/V tiles 32x64 staged in smem (broadcast reads), scores staged in smem
// so j-loops stay runtime-indexed (no local-memory spill of a score array).
// Writes context directly in [B,S,H,dh] == [B,S,D] row-major.
// ---------------------------------------------------------------------------
__global__ void __launch_bounds__(128) attn_kernel(
    const float* __restrict__ Q, const float* __restrict__ Kx,
    const float* __restrict__ V, float* __restrict__ Ctx)
{
    __shared__ float sk[32 * 64];     // 8 KB
    __shared__ float sv[32 * 64];     // 8 KB
    __shared__ float ss[32 * 128];    // 16 KB scores: [j][thread]

    const int t    = threadIdx.x;
    const int bh   = blockIdx.y;
    const int q0   = blockIdx.x * 128;
    const int qrow = q0 + t;

    const float* qp = Q + ((long)bh * SS + qrow) * DH;
    float q[64];
#pragma unroll
    for (int d4 = 0; d4 < 16; d4++) {
        float4 v = *(const float4*)(qp + d4 * 4);
        q[d4 * 4 + 0] = v.x; q[d4 * 4 + 1] = v.y;
        q[d4 * 4 + 2] = v.z; q[d4 * 4 + 3] = v.w;
    }
    float o[64];
#pragma unroll
    for (int d = 0; d < 64; d++) o[d] = 0.f;
    float mrun = -INFINITY, lrun = 0.f;
    const float scale = 0.125f;   // 1/sqrt(64)

    const float* kbase = Kx + (long)bh * SS * DH;
    const float* vbase = V  + (long)bh * SS * DH;
    const int ktiles = (q0 >> 5) + 4;

    for (int kt = 0; kt < ktiles; kt++) {
        const int k0 = kt << 5;
        const float4* ksrc = (const float4*)(kbase + k0 * DH);
        const float4* vsrc = (const float4*)(vbase + k0 * DH);
#pragma unroll
        for (int r = 0; r < 4; r++) {
            ((float4*)sk)[t + r * 128] = ksrc[t + r * 128];
            ((float4*)sv)[t + r * 128] = vsrc[t + r * 128];
        }
        __syncthreads();

        if (k0 <= qrow) {   // this tile has at least one unmasked key for my row
            float tmax = -INFINITY;
#pragma unroll 4
            for (int j = 0; j < 32; j++) {
                const float4* kr = (const float4*)(sk + j * 64);
                float s0 = 0.f, s1 = 0.f, s2 = 0.f, s3 = 0.f;
#pragma unroll
                for (int d4 = 0; d4 < 16; d4++) {
                    float4 kv = kr[d4];
                    s0 = fmaf(q[d4 * 4 + 0], kv.x, s0);
                    s1 = fmaf(q[d4 * 4 + 1], kv.y, s1);
                    s2 = fmaf(q[d4 * 4 + 2], kv.z, s2);
                    s3 = fmaf(q[d4 * 4 + 3], kv.w, s3);
                }
                float s = (s0 + s1) + (s2 + s3);
                s = (k0 + j <= qrow) ? s * scale : -INFINITY;
                ss[j * 128 + t] = s;
                tmax = fmaxf(tmax, s);
            }
            float mnew = fmaxf(mrun, tmax);
            float corr = __expf(mrun - mnew);   // first tile: exp(-inf)=0
#pragma unroll
            for (int d = 0; d < 64; d++) o[d] *= corr;
            lrun *= corr;
#pragma unroll 2
            for (int j = 0; j < 32; j++) {
                float pj = __expf(ss[j * 128 + t] - mnew);
                lrun += pj;
                const float4* vr = (const float4*)(sv + j * 64);
#pragma unroll
                for (int d4 = 0; d4 < 16; d4++) {
                    float4 vv = vr[d4];
                    o[d4 * 4 + 0] = fmaf(pj, vv.x, o[d4 * 4 + 0]);
                    o[d4 * 4 + 1] = fmaf(pj, vv.y, o[d4 * 4 + 1]);
                    o[d4 * 4 + 2] = fmaf(pj, vv.z, o[d4 * 4 + 2]);
                    o[d4 * 4 + 3] = fmaf(pj, vv.w, o[d4 * 4 + 3]);
                }
            }
            mrun = mnew;
        }
        __syncthreads();
    }

    float inv = 1.f / lrun;
    int b = bh >> 4, h = bh & 15;
    float* op = Ctx + (((long)b * SS + qrow) * HH + h) * DH;
#pragma unroll
    for (int d4 = 0; d4 < 16; d4++) {
        float4 v;
        v.x = o[d4 * 4 + 0] * inv; v.y = o[d4 * 4 + 1] * inv;
        v.z = o[d4 * 4 + 2] * inv; v.w = o[d4 * 4 + 3] * inv;
        *(float4*)(op + d4 * 4) = v;
    }
}

// ---------------------------------------------------------------------------
extern "C" void kernel_launch(void* const* d_in, const int* in_sizes, int n_in,
                              void* d_out, int out_size)
{
    (void)in_sizes; (void)n_in; (void)out_size;
    const float* x   = (const float*)d_in[0];   // in_features [B,S,D]
    const int*   pos = (const int*)  d_in[1];   // token_positions [S]
    const float* wq  = (const float*)d_in[2];
    const float* wk  = (const float*)d_in[3];
    const float* wv  = (const float*)d_in[4];
    const float* wo  = (const float*)d_in[5];
    float* out = (float*)d_out;

    float *qb, *kb, *vb, *cb;
    cudaGetSymbolAddress((void**)&qb, g_q);
    cudaGetSymbolAddress((void**)&kb, g_k);
    cudaGetSymbolAddress((void**)&vb, g_v);
    cudaGetSymbolAddress((void**)&cb, g_ctx);

    dim3 gg(DD / 128, (BB * SS) / 128);   // 8 x 64
    gemm_kernel<<<gg, 256>>>(x, wq, qb, pos, 2);   // Q + RoPE, head-major
    gemm_kernel<<<gg, 256>>>(x, wk, kb, pos, 2);   // K + RoPE, head-major
    gemm_kernel<<<gg, 256>>>(x, wv, vb, pos, 1);   // V, head-major

    dim3 ga(SS / 128, BB * HH);           // 16 x 64
    attn_kernel<<<ga, 128>>>(qb, kb, vb, cb);

    gemm_kernel<<<gg, 256>>>(cb, wo, out, pos, 0); // output projection
}